// round 3
// baseline (speedup 1.0000x reference)
#include <cuda_runtime.h>
#include <cstdint>

#define BB   16
#define CC   32
#define HH   256
#define WW   256
#define T2   8
#define NT   (2*T2)
#define CH   16
#define NCH  16
#define FIELD (HH*WW)
#define BT   (BB*T2)

typedef unsigned long long u64;

// ---------------- scratch (no cudaMalloc allowed) ----------------
__device__ __align__(256) float g_w1 [BT*FIELD];
__device__ __align__(256) float g_w2 [BT*FIELD];
__device__ __align__(256) float g_w3 [BT*FIELD];
__device__ __align__(256) float g_w1p[BT*FIELD];
__device__ __align__(256) float g_w2p[BT*FIELD];
__device__ __align__(256) float g_w3p[BT*FIELD];
__device__ __align__(256) float g_gv2[BT*FIELD];
__device__ __align__(256) float g_Sh [BT*3*NCH*2*WW];  // raw chunk colsums (w3,w3p,w2p), 2 row-groups
__device__ __align__(256) float g_S3 [BT*NCH*WW];      // chunk colsums of gv2

// ---------------- f32x2 helpers ----------------
__device__ __forceinline__ u64 fma2(u64 a, u64 b, u64 c) {
    u64 d; asm("fma.rn.f32x2 %0, %1, %2, %3;" : "=l"(d) : "l"(a), "l"(b), "l"(c)); return d;
}
__device__ __forceinline__ u64 add2(u64 a, u64 b) {
    u64 d; asm("add.rn.f32x2 %0, %1, %2;" : "=l"(d) : "l"(a), "l"(b)); return d;
}
__device__ __forceinline__ u64 pack2(float lo, float hi) {
    u64 r; asm("mov.b64 %0, {%1, %2};" : "=l"(r) : "f"(lo), "f"(hi)); return r;
}
__device__ __forceinline__ float2 unpack2(u64 v) {
    float2 f; asm("mov.b64 {%0, %1}, %2;" : "=f"(f.x), "=f"(f.y) : "l"(v)); return f;
}

// ---------------- warp scan: 256 elems, 8 per lane ----------------
// incl[i] = inclusive prefix at element (lane*8+i); returns row total.
__device__ __forceinline__ float wscan8(const float* v, float* incl) {
    float r = 0.f; float tmp[8];
    #pragma unroll
    for (int i = 0; i < 8; i++) { r += v[i]; tmp[i] = r; }
    float s = r;
    const int lane = threadIdx.x & 31;
    #pragma unroll
    for (int d = 1; d < 32; d <<= 1) {
        float n = __shfl_up_sync(0xffffffffu, s, d);
        if (lane >= d) s += n;
    }
    float excl = s - r;
    #pragma unroll
    for (int i = 0; i < 8; i++) incl[i] = tmp[i] + excl;
    return __shfl_sync(0xffffffffu, s, 31);
}

__device__ __forceinline__ void LD8(float* v, const float* p) {
    float4 a = *(const float4*)p, b = *(const float4*)(p + 4);
    v[0]=a.x; v[1]=a.y; v[2]=a.z; v[3]=a.w; v[4]=b.x; v[5]=b.y; v[6]=b.z; v[7]=b.w;
}
__device__ __forceinline__ void ST8(float* p, const float* v) {
    *(float4*)p       = make_float4(v[0],v[1],v[2],v[3]);
    *(float4*)(p + 4) = make_float4(v[4],v[5],v[6],v[7]);
}

// =====================================================================
// K1: pure weighting GEMM + register column-sums. Alphas in smem
// (broadcast LDS.64). One barrier total. No scans.
// grid = (T2/2, NCH, BB), block = 128 (2 row-groups x 64 lanes x 4 cols)
// =====================================================================
__global__ void __launch_bounds__(128) k1_weight(
    const float* __restrict__ x,
    const float* __restrict__ a1,  const float* __restrict__ a2,
    const float* __restrict__ a3,  const float* __restrict__ a1p,
    const float* __restrict__ a2p, const float* __restrict__ a3p)
{
    __shared__ u64 s_al[2][6][CC];

    const int tid = threadIdx.x;
    const int rg  = tid >> 6;          // row-group (even/odd rows)
    const int l   = tid & 63;
    const int col = l * 4;
    const int t0    = blockIdx.x * 2;
    const int chunk = blockIdx.y;
    const int b     = blockIdx.z;
    const int bt0   = b * T2 + t0;

    {
        const float* aptr[6] = {a1, a2, a3, a1p, a2p, a3p};
        for (int i = tid; i < 2 * 6 * CC; i += 128) {
            int c  = i & (CC - 1);
            int f  = (i >> 5) % 6;
            int tr = i / (6 * CC);
            float v = aptr[f][(t0 + tr) * CC + c];
            s_al[tr][f][c] = pack2(v, v);
        }
    }
    __syncthreads();

    u64 cs[2][3][2];
    #pragma unroll
    for (int tr = 0; tr < 2; tr++)
        #pragma unroll
        for (int k = 0; k < 3; k++) { cs[tr][k][0] = 0ull; cs[tr][k][1] = 0ull; }

    #pragma unroll 1
    for (int it = 0; it < 8; it++) {
        const int h = chunk * CH + rg + it * 2;
        u64 acc[2][6][2];
        #pragma unroll
        for (int tr = 0; tr < 2; tr++)
            #pragma unroll
            for (int f = 0; f < 6; f++) { acc[tr][f][0] = 0ull; acc[tr][f][1] = 0ull; }

        const float* xp = x + (size_t)b * CC * FIELD + (size_t)h * WW + col;
        #pragma unroll 8
        for (int c = 0; c < CC; c++) {
            float4 xv = *(const float4*)(xp + (size_t)c * FIELD);
            u64 x01 = pack2(xv.x, xv.y);
            u64 x23 = pack2(xv.z, xv.w);
            #pragma unroll
            for (int tr = 0; tr < 2; tr++)
                #pragma unroll
                for (int f = 0; f < 6; f++) {
                    u64 al = s_al[tr][f][c];        // broadcast LDS.64
                    acc[tr][f][0] = fma2(x01, al, acc[tr][f][0]);
                    acc[tr][f][1] = fma2(x23, al, acc[tr][f][1]);
                }
        }

        #pragma unroll
        for (int tr = 0; tr < 2; tr++) {
            const size_t base = ((size_t)(bt0 + tr) * HH + h) * WW + col;
            float* dst[6] = {g_w1, g_w2, g_w3, g_w1p, g_w2p, g_w3p};
            #pragma unroll
            for (int f = 0; f < 6; f++) {
                float2 lo = unpack2(acc[tr][f][0]);
                float2 hi = unpack2(acc[tr][f][1]);
                *(float4*)&dst[f][base] = make_float4(lo.x, lo.y, hi.x, hi.y);
            }
            // column sums of raw w3, w3p, w2p
            cs[tr][0][0] = add2(cs[tr][0][0], acc[tr][2][0]);
            cs[tr][0][1] = add2(cs[tr][0][1], acc[tr][2][1]);
            cs[tr][1][0] = add2(cs[tr][1][0], acc[tr][5][0]);
            cs[tr][1][1] = add2(cs[tr][1][1], acc[tr][5][1]);
            cs[tr][2][0] = add2(cs[tr][2][0], acc[tr][4][0]);
            cs[tr][2][1] = add2(cs[tr][2][1], acc[tr][4][1]);
        }
    }

    #pragma unroll
    for (int tr = 0; tr < 2; tr++)
        #pragma unroll
        for (int k = 0; k < 3; k++) {
            float2 lo = unpack2(cs[tr][k][0]);
            float2 hi = unpack2(cs[tr][k][1]);
            size_t o = (((size_t)(bt0 + tr) * 3 + k) * NCH + chunk) * 2 * WW + rg * WW + col;
            *(float4*)&g_Sh[o] = make_float4(lo.x, lo.y, hi.x, hi.y);
        }
}

// =====================================================================
// K2: bottom-up. One warp per (chunk,t,b), 8 cols/lane, warp-local scans.
//   v2 = w2 * SW(w3); gv2 = rev-excl-w-scan(v2) (stored)
//   cherry = w1p * SW(w3p) * SE(w2p) -> out
// =====================================================================
__global__ void __launch_bounds__(128) k2_bottomup(float* __restrict__ out)
{
    const int wid  = threadIdx.x >> 5;
    const int lane = threadIdx.x & 31;
    const int gw   = blockIdx.x * 4 + wid;      // 2048 warps
    const int chunk =  gw        & 15;
    const int t     = (gw >> 4)  & 7;
    const int b     =  gw >> 7;
    const int bt    = b * T2 + t;
    const int col   = lane * 8;

    // raw colsums of chunks strictly below
    float s[3][8];
    #pragma unroll
    for (int k = 0; k < 3; k++)
        #pragma unroll
        for (int i = 0; i < 8; i++) s[k][i] = 0.f;

    for (int j = chunk + 1; j < NCH; j++) {
        #pragma unroll
        for (int k = 0; k < 3; k++) {
            const float* R = g_Sh + (((size_t)bt * 3 + k) * NCH + j) * 2 * WW + col;
            float4 a0 = *(const float4*)R,          a1 = *(const float4*)(R + 4);
            float4 b0 = *(const float4*)(R + WW),   b1 = *(const float4*)(R + WW + 4);
            s[k][0] += a0.x + b0.x; s[k][1] += a0.y + b0.y;
            s[k][2] += a0.z + b0.z; s[k][3] += a0.w + b0.w;
            s[k][4] += a1.x + b1.x; s[k][5] += a1.y + b1.y;
            s[k][6] += a1.z + b1.z; s[k][7] += a1.w + b1.w;
        }
    }

    float a3[8], p3[8], p2[8], incl[8];
    {
        wscan8(s[0], incl);
        #pragma unroll
        for (int i = 0; i < 8; i++) a3[i] = incl[i] - s[0][i];
        wscan8(s[1], incl);
        #pragma unroll
        for (int i = 0; i < 8; i++) p3[i] = incl[i] - s[1][i];
        float tot = wscan8(s[2], incl);
        #pragma unroll
        for (int i = 0; i < 8; i++) p2[i] = tot - incl[i];
    }

    float cssum[8];
    #pragma unroll
    for (int i = 0; i < 8; i++) cssum[i] = 0.f;

    #pragma unroll 1
    for (int r = CH - 1; r >= 0; r--) {
        const int h = chunk * CH + r;
        const size_t base = (size_t)bt * FIELD + (size_t)h * WW + col;

        // v2 = w2 * a3 ; gv2 = reverse strict prefix
        float w2v[8]; LD8(w2v, g_w2 + base);
        float v2[8];
        #pragma unroll
        for (int i = 0; i < 8; i++) v2[i] = w2v[i] * a3[i];
        float tot = wscan8(v2, incl);
        float gv[8];
        #pragma unroll
        for (int i = 0; i < 8; i++) { gv[i] = tot - incl[i]; cssum[i] += gv[i]; }
        ST8(g_gv2 + base, gv);

        // cherry output (p3/p2 are strict-south sums, pre-update)
        float w1pv[8]; LD8(w1pv, g_w1p + base);
        float ch[8];
        #pragma unroll
        for (int i = 0; i < 8; i++) ch[i] = w1pv[i] * p3[i] * p2[i];
        ST8(out + ((size_t)(b * NT + T2 + t)) * FIELD + (size_t)h * WW + col, ch);

        // updates: a3 += fwdexcl(w3), p3 += fwdexcl(w3p), p2 += revexcl(w2p)
        float w3v[8]; LD8(w3v, g_w3 + base);
        wscan8(w3v, incl);
        #pragma unroll
        for (int i = 0; i < 8; i++) a3[i] += incl[i] - w3v[i];

        float w3pv[8]; LD8(w3pv, g_w3p + base);
        wscan8(w3pv, incl);
        #pragma unroll
        for (int i = 0; i < 8; i++) p3[i] += incl[i] - w3pv[i];

        float w2pv[8]; LD8(w2pv, g_w2p + base);
        tot = wscan8(w2pv, incl);
        #pragma unroll
        for (int i = 0; i < 8; i++) p2[i] += tot - incl[i];
    }

    ST8(g_S3 + ((size_t)bt * NCH + chunk) * WW + col, cssum);
}

// =====================================================================
// K3: top-down. linear = w1 * NE(v2) = w1 * strict-north colsum of gv2
// =====================================================================
__global__ void __launch_bounds__(128) k3_topdown(float* __restrict__ out)
{
    const int wid  = threadIdx.x >> 5;
    const int lane = threadIdx.x & 31;
    const int gw   = blockIdx.x * 4 + wid;
    const int chunk =  gw        & 15;
    const int t     = (gw >> 4)  & 7;
    const int b     =  gw >> 7;
    const int bt    = b * T2 + t;
    const int col   = lane * 8;

    float va[8];
    #pragma unroll
    for (int i = 0; i < 8; i++) va[i] = 0.f;
    for (int j = 0; j < chunk; j++) {
        const float* p = g_S3 + ((size_t)bt * NCH + j) * WW + col;
        float4 a = *(const float4*)p, bq = *(const float4*)(p + 4);
        va[0] += a.x;  va[1] += a.y;  va[2] += a.z;  va[3] += a.w;
        va[4] += bq.x; va[5] += bq.y; va[6] += bq.z; va[7] += bq.w;
    }

    #pragma unroll 1
    for (int r = 0; r < CH; r++) {
        const int h = chunk * CH + r;
        const size_t base = (size_t)bt * FIELD + (size_t)h * WW + col;
        float w1v[8]; LD8(w1v, g_w1 + base);
        float gv[8];  LD8(gv,  g_gv2 + base);
        float o[8];
        #pragma unroll
        for (int i = 0; i < 8; i++) o[i] = w1v[i] * va[i];
        ST8(out + ((size_t)(b * NT + t)) * FIELD + (size_t)h * WW + col, o);
        #pragma unroll
        for (int i = 0; i < 8; i++) va[i] += gv[i];
    }
}

// =====================================================================
extern "C" void kernel_launch(void* const* d_in, const int* in_sizes, int n_in,
                              void* d_out, int out_size)
{
    const float* x   = (const float*)d_in[0];
    const float* a1  = (const float*)d_in[1];
    const float* a2  = (const float*)d_in[2];
    const float* a3  = (const float*)d_in[3];
    const float* a1p = (const float*)d_in[4];
    const float* a2p = (const float*)d_in[5];
    const float* a3p = (const float*)d_in[6];
    float* out = (float*)d_out;

    dim3 g1(T2 / 2, NCH, BB);                    // (4, 16, 16)
    k1_weight<<<g1, 128>>>(x, a1, a2, a3, a1p, a2p, a3p);
    k2_bottomup<<<BT * NCH / 4, 128>>>(out);     // 512 blocks, 2048 warps
    k3_topdown <<<BT * NCH / 4, 128>>>(out);
}

// round 4
// speedup vs baseline: 1.3872x; 1.3872x over previous
#include <cuda_runtime.h>
#include <cstdint>

#define BB   16
#define CC   32
#define HH   256
#define WW   256
#define T2   8
#define NT   (2*T2)
#define NHC  32               // half-chunks (8 rows each)
#define FIELD (HH*WW)
#define BT   (BB*T2)

typedef unsigned long long u64;

// ---------------- scratch (no cudaMalloc allowed) ----------------
__device__ __align__(256) float g_w1 [BT*FIELD];
__device__ __align__(256) float g_w2 [BT*FIELD];
__device__ __align__(256) float g_w3 [BT*FIELD];
__device__ __align__(256) float g_w1p[BT*FIELD];
__device__ __align__(256) float g_w2p[BT*FIELD];
__device__ __align__(256) float g_w3p[BT*FIELD];
__device__ __align__(256) float g_gv2[BT*FIELD];
__device__ __align__(256) float g_Sh [BT*3*NHC*WW];   // raw halfchunk colsums (w3,w3p,w2p)
__device__ __align__(256) float g_S3 [BT*NHC*WW];     // halfchunk colsums of gv2

// ---------------- f32x2 helpers ----------------
__device__ __forceinline__ u64 fma2(u64 a, u64 b, u64 c) {
    u64 d; asm("fma.rn.f32x2 %0, %1, %2, %3;" : "=l"(d) : "l"(a), "l"(b), "l"(c)); return d;
}
__device__ __forceinline__ u64 add2(u64 a, u64 b) {
    u64 d; asm("add.rn.f32x2 %0, %1, %2;" : "=l"(d) : "l"(a), "l"(b)); return d;
}
__device__ __forceinline__ u64 pack2(float lo, float hi) {
    u64 r; asm("mov.b64 %0, {%1, %2};" : "=l"(r) : "f"(lo), "f"(hi)); return r;
}
__device__ __forceinline__ float2 unpack2(u64 v) {
    float2 f; asm("mov.b64 {%0, %1}, %2;" : "=f"(f.x), "=f"(f.y) : "l"(v)); return f;
}

// ---------------- warp scan: 256 elems, 8 per lane ----------------
__device__ __forceinline__ float wscan8(const float* v, float* incl) {
    float r = 0.f; float tmp[8];
    #pragma unroll
    for (int i = 0; i < 8; i++) { r += v[i]; tmp[i] = r; }
    float s = r;
    const int lane = threadIdx.x & 31;
    #pragma unroll
    for (int d = 1; d < 32; d <<= 1) {
        float n = __shfl_up_sync(0xffffffffu, s, d);
        if (lane >= d) s += n;
    }
    float excl = s - r;
    #pragma unroll
    for (int i = 0; i < 8; i++) incl[i] = tmp[i] + excl;
    return __shfl_sync(0xffffffffu, s, 31);
}

__device__ __forceinline__ void LD8(float* v, const float* p) {
    float4 a = *(const float4*)p, b = *(const float4*)(p + 4);
    v[0]=a.x; v[1]=a.y; v[2]=a.z; v[3]=a.w; v[4]=b.x; v[5]=b.y; v[6]=b.z; v[7]=b.w;
}
__device__ __forceinline__ void ST8(float* p, const float* v) {
    *(float4*)p       = make_float4(v[0],v[1],v[2],v[3]);
    *(float4*)(p + 4) = make_float4(v[4],v[5],v[6],v[7]);
}

// =====================================================================
// K1: weighting GEMM. CTA = 8 rows x 256 w, 2 trees, 6 fields.
// 128 thr: rowoff = tid>>6 (row parity), 64 lanes x 4 cols.
// Alphas: smem [tr][c][f] -> 6 LDS.128 per channel (was 12 LDS.64).
// grid = (T2/2, NHC, BB) = (4, 32, 16) = 2048 CTAs, 4 CTAs/SM.
// =====================================================================
__global__ void __launch_bounds__(128, 4) k1_weight(
    const float* __restrict__ x,
    const float* __restrict__ a1,  const float* __restrict__ a2,
    const float* __restrict__ a3,  const float* __restrict__ a1p,
    const float* __restrict__ a2p, const float* __restrict__ a3p)
{
    __shared__ __align__(16) u64 s_al[2][CC][6];   // [tree][channel][field]
    __shared__ float s_comb[2][3][WW];             // colsum combine buffer

    const int tid    = threadIdx.x;
    const int rowoff = tid >> 6;
    const int lt     = tid & 63;
    const int col    = lt * 4;
    const int t0     = blockIdx.x * 2;
    const int hc     = blockIdx.y;            // half-chunk: rows hc*8 .. hc*8+7
    const int b      = blockIdx.z;
    const int bt0    = b * T2 + t0;

    {
        const float* aptr[6] = {a1, a2, a3, a1p, a2p, a3p};
        for (int i = tid; i < 2 * CC * 6; i += 128) {
            int f  = i % 6;
            int c  = (i / 6) % CC;
            int tr = i / (6 * CC);
            float v = aptr[f][(t0 + tr) * CC + c];
            s_al[tr][c][f] = pack2(v, v);
        }
    }
    __syncthreads();

    u64 cs[2][3][2];
    #pragma unroll
    for (int tr = 0; tr < 2; tr++)
        #pragma unroll
        for (int k = 0; k < 3; k++) { cs[tr][k][0] = 0ull; cs[tr][k][1] = 0ull; }

    #pragma unroll 1
    for (int it = 0; it < 4; it++) {
        const int h = hc * 8 + it * 2 + rowoff;
        u64 acc[2][6][2];
        #pragma unroll
        for (int tr = 0; tr < 2; tr++)
            #pragma unroll
            for (int f = 0; f < 6; f++) { acc[tr][f][0] = 0ull; acc[tr][f][1] = 0ull; }

        const float* xp = x + (size_t)b * CC * FIELD + (size_t)h * WW + col;
        #pragma unroll 4
        for (int c = 0; c < CC; c++) {
            float4 xv = *(const float4*)(xp + (size_t)c * FIELD);
            u64 x01 = pack2(xv.x, xv.y);
            u64 x23 = pack2(xv.z, xv.w);
            #pragma unroll
            for (int tr = 0; tr < 2; tr++) {
                const ulonglong2 pA = *(const ulonglong2*)&s_al[tr][c][0];
                const ulonglong2 pB = *(const ulonglong2*)&s_al[tr][c][2];
                const ulonglong2 pC = *(const ulonglong2*)&s_al[tr][c][4];
                acc[tr][0][0] = fma2(x01, pA.x, acc[tr][0][0]);
                acc[tr][0][1] = fma2(x23, pA.x, acc[tr][0][1]);
                acc[tr][1][0] = fma2(x01, pA.y, acc[tr][1][0]);
                acc[tr][1][1] = fma2(x23, pA.y, acc[tr][1][1]);
                acc[tr][2][0] = fma2(x01, pB.x, acc[tr][2][0]);
                acc[tr][2][1] = fma2(x23, pB.x, acc[tr][2][1]);
                acc[tr][3][0] = fma2(x01, pB.y, acc[tr][3][0]);
                acc[tr][3][1] = fma2(x23, pB.y, acc[tr][3][1]);
                acc[tr][4][0] = fma2(x01, pC.x, acc[tr][4][0]);
                acc[tr][4][1] = fma2(x23, pC.x, acc[tr][4][1]);
                acc[tr][5][0] = fma2(x01, pC.y, acc[tr][5][0]);
                acc[tr][5][1] = fma2(x23, pC.y, acc[tr][5][1]);
            }
        }

        #pragma unroll
        for (int tr = 0; tr < 2; tr++) {
            const size_t base = (size_t)(bt0 + tr) * FIELD + (size_t)h * WW + col;
            float* dst[6] = {g_w1, g_w2, g_w3, g_w1p, g_w2p, g_w3p};
            #pragma unroll
            for (int f = 0; f < 6; f++) {
                float2 lo = unpack2(acc[tr][f][0]);
                float2 hi = unpack2(acc[tr][f][1]);
                *(float4*)&dst[f][base] = make_float4(lo.x, lo.y, hi.x, hi.y);
            }
            cs[tr][0][0] = add2(cs[tr][0][0], acc[tr][2][0]);   // w3
            cs[tr][0][1] = add2(cs[tr][0][1], acc[tr][2][1]);
            cs[tr][1][0] = add2(cs[tr][1][0], acc[tr][5][0]);   // w3p
            cs[tr][1][1] = add2(cs[tr][1][1], acc[tr][5][1]);
            cs[tr][2][0] = add2(cs[tr][2][0], acc[tr][4][0]);   // w2p
            cs[tr][2][1] = add2(cs[tr][2][1], acc[tr][4][1]);
        }
    }

    // combine row-parity partials and store halfchunk colsums
    if (rowoff == 1) {
        #pragma unroll
        for (int tr = 0; tr < 2; tr++)
            #pragma unroll
            for (int k = 0; k < 3; k++) {
                float2 lo = unpack2(cs[tr][k][0]);
                float2 hi = unpack2(cs[tr][k][1]);
                *(float4*)&s_comb[tr][k][col] = make_float4(lo.x, lo.y, hi.x, hi.y);
            }
    }
    __syncthreads();
    if (rowoff == 0) {
        #pragma unroll
        for (int tr = 0; tr < 2; tr++)
            #pragma unroll
            for (int k = 0; k < 3; k++) {
                float4 o = *(const float4*)&s_comb[tr][k][col];
                float2 lo = unpack2(cs[tr][k][0]);
                float2 hi = unpack2(cs[tr][k][1]);
                size_t off = (((size_t)(bt0 + tr) * 3 + k) * NHC + hc) * WW + col;
                *(float4*)&g_Sh[off] = make_float4(lo.x + o.x, lo.y + o.y,
                                                   hi.x + o.z, hi.y + o.w);
            }
    }
}

// =====================================================================
// K2: bottom-up. One warp per (halfchunk,t,b) = 4096 warps, 8 rows each.
//   v2 = w2 * SW(w3); gv2 = rev-excl-w-scan(v2) (stored)
//   cherry = w1p * SW(w3p) * SE(w2p) -> out
// =====================================================================
__global__ void __launch_bounds__(128) k2_bottomup(float* __restrict__ out)
{
    const int wid  = threadIdx.x >> 5;
    const int lane = threadIdx.x & 31;
    const int gw   = blockIdx.x * 4 + wid;      // 4096 warps
    const int half =  gw        & 31;
    const int t    = (gw >> 5)  & 7;
    const int b    =  gw >> 8;
    const int bt   = b * T2 + t;
    const int col  = lane * 8;

    // raw colsums of halfchunks strictly below
    float s[3][8];
    #pragma unroll
    for (int k = 0; k < 3; k++)
        #pragma unroll
        for (int i = 0; i < 8; i++) s[k][i] = 0.f;

    for (int j = half + 1; j < NHC; j++) {
        #pragma unroll
        for (int k = 0; k < 3; k++) {
            const float* R = g_Sh + (((size_t)bt * 3 + k) * NHC + j) * WW + col;
            float4 q0 = *(const float4*)R, q1 = *(const float4*)(R + 4);
            s[k][0] += q0.x; s[k][1] += q0.y; s[k][2] += q0.z; s[k][3] += q0.w;
            s[k][4] += q1.x; s[k][5] += q1.y; s[k][6] += q1.z; s[k][7] += q1.w;
        }
    }

    float a3[8], p3[8], p2[8], incl[8];
    {
        wscan8(s[0], incl);
        #pragma unroll
        for (int i = 0; i < 8; i++) a3[i] = incl[i] - s[0][i];
        wscan8(s[1], incl);
        #pragma unroll
        for (int i = 0; i < 8; i++) p3[i] = incl[i] - s[1][i];
        float tot = wscan8(s[2], incl);
        #pragma unroll
        for (int i = 0; i < 8; i++) p2[i] = tot - incl[i];
    }

    float cssum[8];
    #pragma unroll
    for (int i = 0; i < 8; i++) cssum[i] = 0.f;

    #pragma unroll 1
    for (int r = 7; r >= 0; r--) {
        const int h = half * 8 + r;
        const size_t base = (size_t)bt * FIELD + (size_t)h * WW + col;

        float w2v[8]; LD8(w2v, g_w2 + base);
        float v2[8];
        #pragma unroll
        for (int i = 0; i < 8; i++) v2[i] = w2v[i] * a3[i];
        float tot = wscan8(v2, incl);
        float gv[8];
        #pragma unroll
        for (int i = 0; i < 8; i++) { gv[i] = tot - incl[i]; cssum[i] += gv[i]; }
        ST8(g_gv2 + base, gv);

        float w1pv[8]; LD8(w1pv, g_w1p + base);
        float ch[8];
        #pragma unroll
        for (int i = 0; i < 8; i++) ch[i] = w1pv[i] * p3[i] * p2[i];
        ST8(out + ((size_t)(b * NT + T2 + t)) * FIELD + (size_t)h * WW + col, ch);

        float w3v[8]; LD8(w3v, g_w3 + base);
        wscan8(w3v, incl);
        #pragma unroll
        for (int i = 0; i < 8; i++) a3[i] += incl[i] - w3v[i];

        float w3pv[8]; LD8(w3pv, g_w3p + base);
        wscan8(w3pv, incl);
        #pragma unroll
        for (int i = 0; i < 8; i++) p3[i] += incl[i] - w3pv[i];

        float w2pv[8]; LD8(w2pv, g_w2p + base);
        tot = wscan8(w2pv, incl);
        #pragma unroll
        for (int i = 0; i < 8; i++) p2[i] += tot - incl[i];
    }

    ST8(g_S3 + ((size_t)bt * NHC + half) * WW + col, cssum);
}

// =====================================================================
// K3: top-down. linear = w1 * strict-north colsum of gv2.
// One warp per (halfchunk,t,b) = 4096 warps.
// =====================================================================
__global__ void __launch_bounds__(128) k3_topdown(float* __restrict__ out)
{
    const int wid  = threadIdx.x >> 5;
    const int lane = threadIdx.x & 31;
    const int gw   = blockIdx.x * 4 + wid;
    const int half =  gw        & 31;
    const int t    = (gw >> 5)  & 7;
    const int b    =  gw >> 8;
    const int bt   = b * T2 + t;
    const int col  = lane * 8;

    float va[8];
    #pragma unroll
    for (int i = 0; i < 8; i++) va[i] = 0.f;
    for (int j = 0; j < half; j++) {
        const float* p = g_S3 + ((size_t)bt * NHC + j) * WW + col;
        float4 a = *(const float4*)p, bq = *(const float4*)(p + 4);
        va[0] += a.x;  va[1] += a.y;  va[2] += a.z;  va[3] += a.w;
        va[4] += bq.x; va[5] += bq.y; va[6] += bq.z; va[7] += bq.w;
    }

    #pragma unroll 1
    for (int r = 0; r < 8; r++) {
        const int h = half * 8 + r;
        const size_t base = (size_t)bt * FIELD + (size_t)h * WW + col;
        float w1v[8]; LD8(w1v, g_w1 + base);
        float gv[8];  LD8(gv,  g_gv2 + base);
        float o[8];
        #pragma unroll
        for (int i = 0; i < 8; i++) o[i] = w1v[i] * va[i];
        ST8(out + ((size_t)(b * NT + t)) * FIELD + (size_t)h * WW + col, o);
        #pragma unroll
        for (int i = 0; i < 8; i++) va[i] += gv[i];
    }
}

// =====================================================================
extern "C" void kernel_launch(void* const* d_in, const int* in_sizes, int n_in,
                              void* d_out, int out_size)
{
    const float* x   = (const float*)d_in[0];
    const float* a1  = (const float*)d_in[1];
    const float* a2  = (const float*)d_in[2];
    const float* a3  = (const float*)d_in[3];
    const float* a1p = (const float*)d_in[4];
    const float* a2p = (const float*)d_in[5];
    const float* a3p = (const float*)d_in[6];
    float* out = (float*)d_out;

    dim3 g1(T2 / 2, NHC, BB);                    // (4, 32, 16) = 2048 CTAs
    k1_weight<<<g1, 128>>>(x, a1, a2, a3, a1p, a2p, a3p);
    k2_bottomup<<<BT * NHC / 4, 128>>>(out);     // 1024 blocks, 4096 warps
    k3_topdown <<<BT * NHC / 4, 128>>>(out);
}

// round 5
// speedup vs baseline: 1.4634x; 1.0550x over previous
#include <cuda_runtime.h>
#include <cstdint>

#define BB   16
#define CC   32
#define HH   256
#define WW   256
#define T2   8
#define NT   (2*T2)
#define NHC  32               // half-chunks (8 rows each)
#define FIELD (HH*WW)
#define BT   (BB*T2)

typedef unsigned long long u64;

// ---------------- scratch (no cudaMalloc allowed) ----------------
__device__ __align__(256) float g_w1 [BT*FIELD];
__device__ __align__(256) float g_w2 [BT*FIELD];
__device__ __align__(256) float g_w3 [BT*FIELD];
__device__ __align__(256) float g_w1p[BT*FIELD];
__device__ __align__(256) float g_w2p[BT*FIELD];
__device__ __align__(256) float g_w3p[BT*FIELD];
__device__ __align__(256) float g_gv2[BT*FIELD];
__device__ __align__(256) float g_Sh [BT*3*NHC*WW];   // raw halfchunk colsums (w3,w3p,w2p)
__device__ __align__(256) float g_S3 [BT*NHC*WW];     // halfchunk colsums of gv2
__device__ u64 g_apk[T2*6*CC];                        // packed alphas (staging)
__constant__ u64 c_al[T2*6*CC];                       // packed alphas (uniform const loads)

// ---------------- f32x2 helpers ----------------
__device__ __forceinline__ u64 fma2(u64 a, u64 b, u64 c) {
    u64 d; asm("fma.rn.f32x2 %0, %1, %2, %3;" : "=l"(d) : "l"(a), "l"(b), "l"(c)); return d;
}
__device__ __forceinline__ u64 add2(u64 a, u64 b) {
    u64 d; asm("add.rn.f32x2 %0, %1, %2;" : "=l"(d) : "l"(a), "l"(b)); return d;
}
__device__ __forceinline__ u64 pack2(float lo, float hi) {
    u64 r; asm("mov.b64 %0, {%1, %2};" : "=l"(r) : "f"(lo), "f"(hi)); return r;
}
__device__ __forceinline__ float2 unpack2(u64 v) {
    float2 f; asm("mov.b64 {%0, %1}, %2;" : "=f"(f.x), "=f"(f.y) : "l"(v)); return f;
}

// ---------------- warp scan: 256 elems, 8 per lane ----------------
__device__ __forceinline__ float wscan8(const float* v, float* incl) {
    float r = 0.f; float tmp[8];
    #pragma unroll
    for (int i = 0; i < 8; i++) { r += v[i]; tmp[i] = r; }
    float s = r;
    const int lane = threadIdx.x & 31;
    #pragma unroll
    for (int d = 1; d < 32; d <<= 1) {
        float n = __shfl_up_sync(0xffffffffu, s, d);
        if (lane >= d) s += n;
    }
    float excl = s - r;
    #pragma unroll
    for (int i = 0; i < 8; i++) incl[i] = tmp[i] + excl;
    return __shfl_sync(0xffffffffu, s, 31);
}

__device__ __forceinline__ void LD8(float* v, const float* p) {
    float4 a = *(const float4*)p, b = *(const float4*)(p + 4);
    v[0]=a.x; v[1]=a.y; v[2]=a.z; v[3]=a.w; v[4]=b.x; v[5]=b.y; v[6]=b.z; v[7]=b.w;
}
__device__ __forceinline__ void ST8(float* p, const float* v) {
    *(float4*)p       = make_float4(v[0],v[1],v[2],v[3]);
    *(float4*)(p + 4) = make_float4(v[4],v[5],v[6],v[7]);
}

// =====================================================================
// K0: pack alphas duplicated into f32x2 pairs (staging for c_al)
// =====================================================================
__global__ void k0_pack(const float* __restrict__ a1,  const float* __restrict__ a2,
                        const float* __restrict__ a3,  const float* __restrict__ a1p,
                        const float* __restrict__ a2p, const float* __restrict__ a3p)
{
    int i = blockIdx.x * 256 + threadIdx.x;          // T2*6*CC = 1536
    if (i >= T2 * 6 * CC) return;
    int c = i % CC, f = (i / CC) % 6, t = i / (6 * CC);
    const float* p = (f == 0) ? a1 : (f == 1) ? a2 : (f == 2) ? a3
                   : (f == 3) ? a1p : (f == 4) ? a2p : a3p;
    float v = p[t * CC + c];
    g_apk[(t * 6 + f) * CC + c] = pack2(v, v);
}

// =====================================================================
// K1: weighting GEMM. Alphas from __constant__ (uniform LDCU — no LDS,
// no L1 traffic). Software-pipelined x loads (4 LDG.128 in flight).
// CTA = 8 rows, 2 trees. 128 thr: row parity x 64 lanes x 4 cols.
// grid = (T2/2, NHC, BB) = 2048 CTAs, 4 CTAs/SM.
// =====================================================================
__global__ void __launch_bounds__(128, 4) k1_weight(const float* __restrict__ x)
{
    __shared__ float s_comb[2][3][WW];             // colsum combine buffer

    const int tid    = threadIdx.x;
    const int rowoff = tid >> 6;
    const int lt     = tid & 63;
    const int col    = lt * 4;
    const int t0     = blockIdx.x * 2;
    const int hc     = blockIdx.y;            // rows hc*8 .. hc*8+7
    const int b      = blockIdx.z;
    const int bt0    = b * T2 + t0;

    u64 cs[2][3][2];
    #pragma unroll
    for (int tr = 0; tr < 2; tr++)
        #pragma unroll
        for (int k = 0; k < 3; k++) { cs[tr][k][0] = 0ull; cs[tr][k][1] = 0ull; }

    #pragma unroll 1
    for (int it = 0; it < 4; it++) {
        const int h = hc * 8 + it * 2 + rowoff;
        u64 acc[2][6][2];
        #pragma unroll
        for (int tr = 0; tr < 2; tr++)
            #pragma unroll
            for (int f = 0; f < 6; f++) { acc[tr][f][0] = 0ull; acc[tr][f][1] = 0ull; }

        const float4* xq = (const float4*)(x + (size_t)b * CC * FIELD + (size_t)h * WW + col);
        float4 xb[4];
        #pragma unroll
        for (int c = 0; c < 4; c++) xb[c] = xq[(size_t)c * (FIELD / 4)];

        #pragma unroll
        for (int cb = 0; cb < 8; cb++) {
            float4 xn[4];
            if (cb < 7) {
                #pragma unroll
                for (int c = 0; c < 4; c++)
                    xn[c] = xq[(size_t)(cb * 4 + 4 + c) * (FIELD / 4)];
            }
            #pragma unroll
            for (int c = 0; c < 4; c++) {
                const int cc = cb * 4 + c;
                u64 x01 = pack2(xb[c].x, xb[c].y);
                u64 x23 = pack2(xb[c].z, xb[c].w);
                #pragma unroll
                for (int tr = 0; tr < 2; tr++)
                    #pragma unroll
                    for (int f = 0; f < 6; f++) {
                        u64 al = c_al[((t0 + tr) * 6 + f) * CC + cc];  // uniform const
                        acc[tr][f][0] = fma2(x01, al, acc[tr][f][0]);
                        acc[tr][f][1] = fma2(x23, al, acc[tr][f][1]);
                    }
            }
            if (cb < 7) {
                #pragma unroll
                for (int c = 0; c < 4; c++) xb[c] = xn[c];
            }
        }

        #pragma unroll
        for (int tr = 0; tr < 2; tr++) {
            const size_t base = (size_t)(bt0 + tr) * FIELD + (size_t)h * WW + col;
            float* dst[6] = {g_w1, g_w2, g_w3, g_w1p, g_w2p, g_w3p};
            #pragma unroll
            for (int f = 0; f < 6; f++) {
                float2 lo = unpack2(acc[tr][f][0]);
                float2 hi = unpack2(acc[tr][f][1]);
                *(float4*)&dst[f][base] = make_float4(lo.x, lo.y, hi.x, hi.y);
            }
            cs[tr][0][0] = add2(cs[tr][0][0], acc[tr][2][0]);   // w3
            cs[tr][0][1] = add2(cs[tr][0][1], acc[tr][2][1]);
            cs[tr][1][0] = add2(cs[tr][1][0], acc[tr][5][0]);   // w3p
            cs[tr][1][1] = add2(cs[tr][1][1], acc[tr][5][1]);
            cs[tr][2][0] = add2(cs[tr][2][0], acc[tr][4][0]);   // w2p
            cs[tr][2][1] = add2(cs[tr][2][1], acc[tr][4][1]);
        }
    }

    // combine row-parity partials and store halfchunk colsums
    if (rowoff == 1) {
        #pragma unroll
        for (int tr = 0; tr < 2; tr++)
            #pragma unroll
            for (int k = 0; k < 3; k++) {
                float2 lo = unpack2(cs[tr][k][0]);
                float2 hi = unpack2(cs[tr][k][1]);
                *(float4*)&s_comb[tr][k][col] = make_float4(lo.x, lo.y, hi.x, hi.y);
            }
    }
    __syncthreads();
    if (rowoff == 0) {
        #pragma unroll
        for (int tr = 0; tr < 2; tr++)
            #pragma unroll
            for (int k = 0; k < 3; k++) {
                float4 o = *(const float4*)&s_comb[tr][k][col];
                float2 lo = unpack2(cs[tr][k][0]);
                float2 hi = unpack2(cs[tr][k][1]);
                size_t off = (((size_t)(bt0 + tr) * 3 + k) * NHC + hc) * WW + col;
                *(float4*)&g_Sh[off] = make_float4(lo.x + o.x, lo.y + o.y,
                                                   hi.x + o.z, hi.y + o.w);
            }
    }
}

// =====================================================================
// K2: bottom-up. One warp per (halfchunk,t,b) = 4096 warps, 8 rows each.
// =====================================================================
__global__ void __launch_bounds__(128) k2_bottomup(float* __restrict__ out)
{
    const int wid  = threadIdx.x >> 5;
    const int lane = threadIdx.x & 31;
    const int gw   = blockIdx.x * 4 + wid;      // 4096 warps
    const int half =  gw        & 31;
    const int t    = (gw >> 5)  & 7;
    const int b    =  gw >> 8;
    const int bt   = b * T2 + t;
    const int col  = lane * 8;

    float s[3][8];
    #pragma unroll
    for (int k = 0; k < 3; k++)
        #pragma unroll
        for (int i = 0; i < 8; i++) s[k][i] = 0.f;

    for (int j = half + 1; j < NHC; j++) {
        #pragma unroll
        for (int k = 0; k < 3; k++) {
            const float* R = g_Sh + (((size_t)bt * 3 + k) * NHC + j) * WW + col;
            float4 q0 = *(const float4*)R, q1 = *(const float4*)(R + 4);
            s[k][0] += q0.x; s[k][1] += q0.y; s[k][2] += q0.z; s[k][3] += q0.w;
            s[k][4] += q1.x; s[k][5] += q1.y; s[k][6] += q1.z; s[k][7] += q1.w;
        }
    }

    float a3[8], p3[8], p2[8], incl[8];
    {
        wscan8(s[0], incl);
        #pragma unroll
        for (int i = 0; i < 8; i++) a3[i] = incl[i] - s[0][i];
        wscan8(s[1], incl);
        #pragma unroll
        for (int i = 0; i < 8; i++) p3[i] = incl[i] - s[1][i];
        float tot = wscan8(s[2], incl);
        #pragma unroll
        for (int i = 0; i < 8; i++) p2[i] = tot - incl[i];
    }

    float cssum[8];
    #pragma unroll
    for (int i = 0; i < 8; i++) cssum[i] = 0.f;

    #pragma unroll 1
    for (int r = 7; r >= 0; r--) {
        const int h = half * 8 + r;
        const size_t base = (size_t)bt * FIELD + (size_t)h * WW + col;

        float w2v[8]; LD8(w2v, g_w2 + base);
        float v2[8];
        #pragma unroll
        for (int i = 0; i < 8; i++) v2[i] = w2v[i] * a3[i];
        float tot = wscan8(v2, incl);
        float gv[8];
        #pragma unroll
        for (int i = 0; i < 8; i++) { gv[i] = tot - incl[i]; cssum[i] += gv[i]; }
        ST8(g_gv2 + base, gv);

        float w1pv[8]; LD8(w1pv, g_w1p + base);
        float ch[8];
        #pragma unroll
        for (int i = 0; i < 8; i++) ch[i] = w1pv[i] * p3[i] * p2[i];
        ST8(out + ((size_t)(b * NT + T2 + t)) * FIELD + (size_t)h * WW + col, ch);

        float w3v[8]; LD8(w3v, g_w3 + base);
        wscan8(w3v, incl);
        #pragma unroll
        for (int i = 0; i < 8; i++) a3[i] += incl[i] - w3v[i];

        float w3pv[8]; LD8(w3pv, g_w3p + base);
        wscan8(w3pv, incl);
        #pragma unroll
        for (int i = 0; i < 8; i++) p3[i] += incl[i] - w3pv[i];

        float w2pv[8]; LD8(w2pv, g_w2p + base);
        tot = wscan8(w2pv, incl);
        #pragma unroll
        for (int i = 0; i < 8; i++) p2[i] += tot - incl[i];
    }

    ST8(g_S3 + ((size_t)bt * NHC + half) * WW + col, cssum);
}

// =====================================================================
// K3: top-down. linear = w1 * strict-north colsum of gv2.
// =====================================================================
__global__ void __launch_bounds__(128) k3_topdown(float* __restrict__ out)
{
    const int wid  = threadIdx.x >> 5;
    const int lane = threadIdx.x & 31;
    const int gw   = blockIdx.x * 4 + wid;
    const int half =  gw        & 31;
    const int t    = (gw >> 5)  & 7;
    const int b    =  gw >> 8;
    const int bt   = b * T2 + t;
    const int col  = lane * 8;

    float va[8];
    #pragma unroll
    for (int i = 0; i < 8; i++) va[i] = 0.f;
    for (int j = 0; j < half; j++) {
        const float* p = g_S3 + ((size_t)bt * NHC + j) * WW + col;
        float4 a = *(const float4*)p, bq = *(const float4*)(p + 4);
        va[0] += a.x;  va[1] += a.y;  va[2] += a.z;  va[3] += a.w;
        va[4] += bq.x; va[5] += bq.y; va[6] += bq.z; va[7] += bq.w;
    }

    #pragma unroll 1
    for (int r = 0; r < 8; r++) {
        const int h = half * 8 + r;
        const size_t base = (size_t)bt * FIELD + (size_t)h * WW + col;
        float w1v[8]; LD8(w1v, g_w1 + base);
        float gv[8];  LD8(gv,  g_gv2 + base);
        float o[8];
        #pragma unroll
        for (int i = 0; i < 8; i++) o[i] = w1v[i] * va[i];
        ST8(out + ((size_t)(b * NT + t)) * FIELD + (size_t)h * WW + col, o);
        #pragma unroll
        for (int i = 0; i < 8; i++) va[i] += gv[i];
    }
}

// =====================================================================
extern "C" void kernel_launch(void* const* d_in, const int* in_sizes, int n_in,
                              void* d_out, int out_size)
{
    const float* x   = (const float*)d_in[0];
    const float* a1  = (const float*)d_in[1];
    const float* a2  = (const float*)d_in[2];
    const float* a3  = (const float*)d_in[3];
    const float* a1p = (const float*)d_in[4];
    const float* a2p = (const float*)d_in[5];
    const float* a3p = (const float*)d_in[6];
    float* out = (float*)d_out;

    k0_pack<<<6, 256>>>(a1, a2, a3, a1p, a2p, a3p);

    // Stage packed alphas into __constant__ c_al (device-to-device, capturable).
    void* src = nullptr; void* dst = nullptr;
    cudaGetSymbolAddress(&src, g_apk);
    cudaGetSymbolAddress(&dst, c_al);
    cudaMemcpyAsync(dst, src, sizeof(u64) * T2 * 6 * CC,
                    cudaMemcpyDeviceToDevice, 0);

    dim3 g1(T2 / 2, NHC, BB);                    // (4, 32, 16) = 2048 CTAs
    k1_weight<<<g1, 128>>>(x);
    k2_bottomup<<<BT * NHC / 4, 128>>>(out);     // 1024 blocks, 4096 warps
    k3_topdown <<<BT * NHC / 4, 128>>>(out);
}